// round 5
// baseline (speedup 1.0000x reference)
#include <cuda_runtime.h>
#include <cuda_bf16.h>

// out[b,c,h,w] = alpha[slot[b,h,w], c] * x[b,c,h,w] + beta[slot[b,h,w], c]
//   x, out     : [B=32, C=2048, H=32, W=32] fp32   (256 MB each, streaming)
//   slot_assign: [B, 32, 32] int32 in [0,256)
//   alpha,beta : [256, 2048] fp32                  (2 MB each; gathers must hit L1)

#define B_DIM    32
#define C_DIM    2048
#define HW_DIM   1024          // 32*32
#define CCHUNK   32            // channels per block: 255-slot x 32ch table set = 64KB -> L1-resident
#define TPB      256           // each thread: 4 contiguous pixels x 32 channels

struct f4v { float v[4]; };

// Read-only 128-bit load, caches in L1 (tables: high reuse, keep resident).
__device__ __forceinline__ f4v ld128_nc(const float* p) {
    f4v r;
    asm volatile("ld.global.nc.v4.f32 {%0,%1,%2,%3}, [%4];"
        : "=f"(r.v[0]), "=f"(r.v[1]), "=f"(r.v[2]), "=f"(r.v[3]) : "l"(p));
    return r;
}

// L2-only 128-bit load (x is streaming: do not evict the table set from L1).
__device__ __forceinline__ f4v ld128_cg(const float* p) {
    f4v r;
    asm volatile("ld.global.cg.v4.f32 {%0,%1,%2,%3}, [%4];"
        : "=f"(r.v[0]), "=f"(r.v[1]), "=f"(r.v[2]), "=f"(r.v[3]) : "l"(p));
    return r;
}

// Streaming 128-bit store.
__device__ __forceinline__ void st128_cs(float* p, const f4v& o) {
    asm volatile("st.global.cs.v4.f32 [%0], {%1,%2,%3,%4};"
        :: "l"(p), "f"(o.v[0]), "f"(o.v[1]), "f"(o.v[2]), "f"(o.v[3]) : "memory");
}

__global__ __launch_bounds__(TPB, 3)
void film_slot_kernel(const float* __restrict__ x,
                      const int*   __restrict__ slot,
                      const float* __restrict__ alpha,
                      const float* __restrict__ beta,
                      float*       __restrict__ out)
{
    const int b   = blockIdx.y;               // whole image per block (max slot reuse)
    const int c0  = blockIdx.x * CCHUNK;      // 32-channel chunk
    const int hw4 = threadIdx.x * 4;          // 4 contiguous pixels

    // Per-pixel slot ids (constant across all channels).
    const int4 s4 = *reinterpret_cast<const int4*>(slot + b * HW_DIM + hw4);

    const float* __restrict__ a0 = alpha + (size_t)s4.x * C_DIM;
    const float* __restrict__ a1 = alpha + (size_t)s4.y * C_DIM;
    const float* __restrict__ a2 = alpha + (size_t)s4.z * C_DIM;
    const float* __restrict__ a3 = alpha + (size_t)s4.w * C_DIM;
    const float* __restrict__ b0 = beta  + (size_t)s4.x * C_DIM;
    const float* __restrict__ b1 = beta  + (size_t)s4.y * C_DIM;
    const float* __restrict__ b2 = beta  + (size_t)s4.z * C_DIM;
    const float* __restrict__ b3 = beta  + (size_t)s4.w * C_DIM;

    const float* __restrict__ xb = x   + (size_t)b * (C_DIM * HW_DIM);
    float*       __restrict__ ob = out + (size_t)b * (C_DIM * HW_DIM);

    #pragma unroll 2
    for (int cg = 0; cg < CCHUNK / 4; ++cg) {
        const int c = c0 + cg * 4;

        // 4 channels of (alpha, beta) per pixel: 32 live table regs.
        f4v A0 = ld128_nc(a0 + c);
        f4v A1 = ld128_nc(a1 + c);
        f4v A2 = ld128_nc(a2 + c);
        f4v A3 = ld128_nc(a3 + c);
        f4v B0 = ld128_nc(b0 + c);
        f4v B1 = ld128_nc(b1 + c);
        f4v B2 = ld128_nc(b2 + c);
        f4v B3 = ld128_nc(b3 + c);

        #pragma unroll
        for (int j = 0; j < 4; ++j) {
            const size_t off = (size_t)(c + j) * HW_DIM + hw4;
            const f4v xv = ld128_cg(xb + off);
            f4v o;
            o.v[0] = fmaf(A0.v[j], xv.v[0], B0.v[j]);
            o.v[1] = fmaf(A1.v[j], xv.v[1], B1.v[j]);
            o.v[2] = fmaf(A2.v[j], xv.v[2], B2.v[j]);
            o.v[3] = fmaf(A3.v[j], xv.v[3], B3.v[j]);
            st128_cs(ob + off, o);
        }
    }
}

extern "C" void kernel_launch(void* const* d_in, const int* in_sizes, int n_in,
                              void* d_out, int out_size)
{
    const float* x     = (const float*)d_in[0];
    const int*   slot  = (const int*)  d_in[1];
    const float* alpha = (const float*)d_in[2];
    const float* beta  = (const float*)d_in[3];
    float*       out   = (float*)      d_out;

    dim3 grid(C_DIM / CCHUNK, B_DIM);   // (64, 32) = 2048 blocks
    dim3 block(TPB);                    // 256 threads, each: 4 px x 32 ch
    film_slot_kernel<<<grid, block>>>(x, slot, alpha, beta, out);
}

// round 8
// speedup vs baseline: 1.9223x; 1.9223x over previous
#include <cuda_runtime.h>
#include <cuda_bf16.h>

// out[b,c,h,w] = alpha[slot[b,h,w], c] * x[b,c,h,w] + beta[slot[b,h,w], c]
//   x, out     : [B=32, C=2048, H=32, W=32] fp32   (256 MB each, streaming)
//   slot_assign: [B, 32, 32] int32 in [0,256)
//   alpha,beta : [256, 2048] fp32
//
// Strategy: no divergent global gathers. Each block stages the FULL 256-slot
// table for its 16-channel chunk into 32KB smem (coalesced), then lookups are
// LDS.128. Block = whole image -> slot int4 per thread, x/out float4 coalesced.

#define B_DIM    32
#define C_DIM    2048
#define HW_DIM   1024          // 32*32
#define NSLOTS   256
#define CCHUNK   16            // channels per block
#define TPB      256           // each thread: 4 px x 16 ch = 64 elements

__device__ __forceinline__ void st128_cs(float* p, float a, float b, float c, float d) {
    asm volatile("st.global.cs.v4.f32 [%0], {%1,%2,%3,%4};"
        :: "l"(p), "f"(a), "f"(b), "f"(c), "f"(d) : "memory");
}

__global__ __launch_bounds__(TPB)
void film_slot_kernel(const float* __restrict__ x,
                      const int*   __restrict__ slot,
                      const float* __restrict__ alpha,
                      const float* __restrict__ beta,
                      float*       __restrict__ out)
{
    // tab[jp][s] = {alpha[s][c0+2jp], beta[s][c0+2jp], alpha[s][c0+2jp+1], beta[s][c0+2jp+1]}
    __shared__ float4 tab[CCHUNK / 2][NSLOTS];   // 8 * 256 * 16B = 32 KB

    const int t  = threadIdx.x;
    const int b  = blockIdx.y;
    const int c0 = blockIdx.x * CCHUNK;

    // ---- Stage tables: 4 threads per slot row, 4 passes over 256 rows ----
    {
        const int q = t & 3;                // which 4-channel quarter
        #pragma unroll
        for (int pass = 0; pass < 4; ++pass) {
            const int s = pass * 64 + (t >> 2);
            const float4 av = __ldg(reinterpret_cast<const float4*>(alpha + (size_t)s * C_DIM + c0 + q * 4));
            const float4 bv = __ldg(reinterpret_cast<const float4*>(beta  + (size_t)s * C_DIM + c0 + q * 4));
            tab[2 * q    ][s] = make_float4(av.x, bv.x, av.y, bv.y);
            tab[2 * q + 1][s] = make_float4(av.z, bv.z, av.w, bv.w);
        }
    }

    // Per-pixel slot ids for this thread's 4 contiguous pixels.
    const int  hw4 = t * 4;
    const int4 s4  = *reinterpret_cast<const int4*>(slot + b * HW_DIM + hw4);

    __syncthreads();

    const float* __restrict__ xb = x   + (size_t)b * (C_DIM * HW_DIM);
    float*       __restrict__ ob = out + (size_t)b * (C_DIM * HW_DIM);

    // ---- Compute: 8 channel-pairs ----
    #pragma unroll 2
    for (int jp = 0; jp < CCHUNK / 2; ++jp) {
        // (alpha,beta) for 2 channels x this thread's 4 pixels: 4 LDS.128.
        const float4 t0 = tab[jp][s4.x];
        const float4 t1 = tab[jp][s4.y];
        const float4 t2 = tab[jp][s4.z];
        const float4 t3 = tab[jp][s4.w];

        const size_t off0 = (size_t)(c0 + 2 * jp) * HW_DIM + hw4;

        // channel c0 + 2*jp  (a = .x, b = .y)
        {
            const float4 xv = *reinterpret_cast<const float4*>(xb + off0);
            st128_cs(ob + off0,
                     fmaf(t0.x, xv.x, t0.y),
                     fmaf(t1.x, xv.y, t1.y),
                     fmaf(t2.x, xv.z, t2.y),
                     fmaf(t3.x, xv.w, t3.y));
        }
        // channel c0 + 2*jp + 1  (a = .z, b = .w)
        {
            const size_t off1 = off0 + HW_DIM;
            const float4 xv = *reinterpret_cast<const float4*>(xb + off1);
            st128_cs(ob + off1,
                     fmaf(t0.z, xv.x, t0.w),
                     fmaf(t1.z, xv.y, t1.w),
                     fmaf(t2.z, xv.z, t2.w),
                     fmaf(t3.z, xv.w, t3.w));
        }
    }
}

extern "C" void kernel_launch(void* const* d_in, const int* in_sizes, int n_in,
                              void* d_out, int out_size)
{
    const float* x     = (const float*)d_in[0];
    const int*   slot  = (const int*)  d_in[1];
    const float* alpha = (const float*)d_in[2];
    const float* beta  = (const float*)d_in[3];
    float*       out   = (float*)      d_out;

    dim3 grid(C_DIM / CCHUNK, B_DIM);   // (128, 32) = 4096 blocks
    dim3 block(TPB);
    film_slot_kernel<<<grid, block>>>(x, slot, alpha, beta, out);
}